// round 3
// baseline (speedup 1.0000x reference)
#include <cuda_runtime.h>

#define DD 8
#define TILE 16

// out[n,m] = sigma0 * E0 * ( S + corr )
//   d_k  = (x1[n,k]-x2[m,k])^2
//   E_a  = exp(-0.5 * sum_k d_k * inv2[a,k])          (inv2 = 1/L^2)
//   S    = sum_{c,j} K[c,j]*(Minv[c,j]-d_c)*(lj2[j]-d_j)*E_c*E_j
//   corr = sum_l ( F[l]*poly_l - K[l,l]*(Minv[l,l]-d_l)*(lj2[l]-d_l) ) * E_l^2
// with K[c,j] = sigma[j]/lj2[j]^2 * M[c,j]^2,  M[c,j] = inv2[0,c]+inv2[j,c],
//      lj2[j] = L[0,j]^2, tl = M[l,l], poly_l = -d_l*(5tl+lj2*tl^2)+tl^2*d_l^2+2+lj2*tl

__global__ __launch_bounds__(256) void taylor_rbf_kernel(
    const float* __restrict__ x1, const float* __restrict__ x2,
    const float* __restrict__ L, const float* __restrict__ sig,
    float* __restrict__ out, int N, int M)
{
    __shared__ float w[DD][DD];    // -0.5*log2(e)*inv2[a][k]  (exp2 weights)
    __shared__ float Km[DD][DD];   // K[c][j]
    __shared__ float KMm[DD][DD];  // K[c][j]*Minv[c][j]
    __shared__ float lj2s[DD], c1s[DD], c2s[DD], c3s[DD], Fs[DD], Kds[DD], Mds[DD];
    __shared__ float x1s[TILE][DD + 1], x2s[TILE][DD + 1];
    __shared__ float sig0s;

    const int tid = threadIdx.y * TILE + threadIdx.x;

    // ---- per-block constant derivation (64 threads, ~200 flops, negligible) ----
    if (tid < 64) {
        int c = tid >> 3, j = tid & 7;
        float Ljc = L[j * DD + c];
        float inv2_jc = 1.0f / (Ljc * Ljc);
        float L0c = L[c];
        float inv2_0c = 1.0f / (L0c * L0c);
        float Mcj = inv2_0c + inv2_jc;          // M[c][j]
        float L0j = L[j];
        float lj2 = L0j * L0j;                  // lj2[j]
        float Kcj = sig[j] / (lj2 * lj2) * Mcj * Mcj;
        Km[c][j]  = Kcj;
        KMm[c][j] = Kcj / Mcj;
        // exp2 weights: reuse (c,j) as (a,k)
        float Lak = L[c * DD + j];
        w[c][j] = -0.5f * 1.44269504088896340736f / (Lak * Lak);
        if (c == j) {
            int l = c;
            float tl = Mcj;                     // inv2[0,l] + inv2[l,l]
            c1s[l] = 5.0f * tl + lj2 * tl * tl;
            c2s[l] = tl * tl;
            c3s[l] = 2.0f + lj2 * tl;
            Fs[l]  = sig[l] / (lj2 * lj2);
            Kds[l] = Kcj;
            Mds[l] = 1.0f / Mcj;
            lj2s[l] = lj2;
        }
        if (tid == 0) sig0s = sig[0];
    }

    // ---- stage x tiles (128 floats each) ----
    const int n0 = blockIdx.y * TILE, m0 = blockIdx.x * TILE;
    if (tid < 128) {
        int r = tid >> 3, k = tid & 7;
        int n = n0 + r;
        x1s[r][k] = (n < N) ? x1[n * DD + k] : 0.0f;
    } else {
        int t = tid - 128;
        int r = t >> 3, k = t & 7;
        int m = m0 + r;
        x2s[r][k] = (m < M) ? x2[m * DD + k] : 0.0f;
    }
    __syncthreads();

    const int n = n0 + threadIdx.y, m = m0 + threadIdx.x;
    if (n >= N || m >= M) return;

    float d[DD];
#pragma unroll
    for (int k = 0; k < DD; k++) {
        float t = x1s[threadIdx.y][k] - x2s[threadIdx.x][k];
        d[k] = t * t;
    }

    float E[DD];
#pragma unroll
    for (int a = 0; a < DD; a++) {
        float s = 0.0f;
#pragma unroll
        for (int k = 0; k < DD; k++) s = fmaf(d[k], w[a][k], s);
        E[a] = exp2f(s);
    }

    float Q[DD];
#pragma unroll
    for (int c = 0; c < DD; c++) Q[c] = d[c] * E[c];

    float S = 0.0f;
#pragma unroll
    for (int j = 0; j < DD; j++) {
        float acc = 0.0f;
#pragma unroll
        for (int c = 0; c < DD; c++) {
            acc = fmaf(KMm[c][j], E[c], acc);
            acc = fmaf(-Km[c][j], Q[c], acc);
        }
        S = fmaf(acc, E[j] * (lj2s[j] - d[j]), S);
    }

    float corr = 0.0f;
#pragma unroll
    for (int l = 0; l < DD; l++) {
        float E2 = E[l] * E[l];
        float poly = fmaf(d[l], fmaf(c2s[l], d[l], -c1s[l]), c3s[l]);
        float dd = Fs[l] * poly;
        float oll = Kds[l] * (Mds[l] - d[l]) * (lj2s[l] - d[l]);
        corr = fmaf(dd - oll, E2, corr);
    }

    out[n * M + m] = sig0s * E[0] * (S + corr);
}

extern "C" void kernel_launch(void* const* d_in, const int* in_sizes, int n_in,
                              void* d_out, int out_size)
{
    const float* x1  = (const float*)d_in[0];
    const float* x2  = (const float*)d_in[1];
    const float* L   = (const float*)d_in[2];
    const float* sig = (const float*)d_in[3];
    float* out = (float*)d_out;

    int N = in_sizes[0] / DD;
    int M = in_sizes[1] / DD;

    dim3 block(TILE, TILE);
    dim3 grid((M + TILE - 1) / TILE, (N + TILE - 1) / TILE);
    taylor_rbf_kernel<<<grid, block>>>(x1, x2, L, sig, out, N, M);
}

// round 4
// speedup vs baseline: 1.2798x; 1.2798x over previous
#include <cuda_runtime.h>

#define DD 8
#define TN 16   // n rows per block (threadIdx.y)
#define TM 32   // m cols per block (threadIdx.x covers pairs: m = m0 + 2*tx + {0,1})

typedef unsigned long long u64;

// packed f32x2 ops (Blackwell sm_103a)
#define FMA2(d,a,b,c) asm("fma.rn.f32x2 %0, %1, %2, %3;" : "=l"(d) : "l"(a), "l"(b), "l"(c))
#define MUL2(d,a,b)   asm("mul.rn.f32x2 %0, %1, %2;"     : "=l"(d) : "l"(a), "l"(b))
#define ADD2(d,a,b)   asm("add.rn.f32x2 %0, %1, %2;"     : "=l"(d) : "l"(a), "l"(b))

__device__ __forceinline__ u64 pack2(float lo, float hi) {
    u64 r;
    asm("mov.b64 %0, {%1, %2};" : "=l"(r) : "f"(lo), "f"(hi));
    return r;
}
__device__ __forceinline__ void unpack2(u64 v, float& lo, float& hi) {
    asm("mov.b64 {%0, %1}, %2;" : "=f"(lo), "=f"(hi) : "l"(v));
}
__device__ __forceinline__ float ex2a(float x) {
    float r;
    asm("ex2.approx.f32 %0, %1;" : "=f"(r) : "f"(x));
    return r;
}
__device__ __forceinline__ u64 dup(float v) {
    unsigned u = __float_as_uint(v);
    return ((u64)u << 32) | (u64)u;
}

// Math (identical to the passing R3 kernel, repacked):
//   out[n,m] = sigma0 * E0 * ( S + corr )
//   d_k = (x1[n,k]-x2[m,k])^2 ; E_a = exp2( sum_k d_k * w[a,k] ), w = -0.5*log2e/L^2
//   S   = sum_j [ sum_c (KMm[c,j] E_c - Km[c,j] d_c E_c) ] * E_j * (lj2_j - d_j)
//   corr= sum_l ( F_l*poly_l - Kd_l*(Md_l-d_l)*(lj2_l-d_l) ) * E_l^2
//   poly_l = d_l*(c2_l*d_l - c1_l) + c3_l

__global__ __launch_bounds__(256) void taylor_rbf_kernel(
    const float* __restrict__ x1, const float* __restrict__ x2,
    const float* __restrict__ L, const float* __restrict__ sig,
    float* __restrict__ out, int N, int M)
{
    // all constants stored DUPLICATED (c,c) as u64; 16B-aligned for LDS.128 pairs
    __shared__ __align__(16) u64 wD[DD * DD];      // wD[a*8+k]      = dup(w[a][k])
    __shared__ __align__(16) u64 ksD[DD * 16];     // ksD[j*16+c]    = dup(KMm[c][j]);  ksD[j*16+8+c] = dup(-Km[c][j])
    __shared__ __align__(16) u64 plD[DD * 8];      // per l: (-c1, c2, c3, F, -Kd, Md, lj2, 0)
    __shared__ __align__(16) u64 x1d[TN * DD];     // dup(x1[n0+r][k])
    __shared__ __align__(16) u64 nx2[DD * (TM/2)]; // nx2[k*16+p] = (-x2[m0+2p][k], -x2[m0+2p+1][k])
    __shared__ u64 sig0d;

    const int tx = threadIdx.x;          // 0..15
    const int ty = threadIdx.y;          // 0..15
    const int tid = ty * TN + tx;

    // ---- per-block constant derivation ----
    if (tid < 64) {
        int c = tid >> 3, j = tid & 7;
        float Ljc = L[j * DD + c];
        float inv2_jc = 1.0f / (Ljc * Ljc);
        float L0c = L[c];
        float inv2_0c = 1.0f / (L0c * L0c);
        float Mcj = inv2_0c + inv2_jc;                    // M[c][j]
        float L0j = L[j];
        float lj2 = L0j * L0j;
        float Kcj = sig[j] / (lj2 * lj2) * Mcj * Mcj;
        ksD[j * 16 + c]     = dup(Kcj / Mcj);             // KMm
        ksD[j * 16 + 8 + c] = dup(-Kcj);                  // -Km
        // exp2 weights (reuse (c,j) as (a,k))
        float Lak = L[c * DD + j];
        wD[c * DD + j] = dup(-0.5f * 1.44269504088896340736f / (Lak * Lak));
        if (c == j) {
            int l = c;
            float tl = Mcj;
            plD[l * 8 + 0] = dup(-(5.0f * tl + lj2 * tl * tl));  // -c1
            plD[l * 8 + 1] = dup(tl * tl);                       //  c2
            plD[l * 8 + 2] = dup(2.0f + lj2 * tl);               //  c3
            plD[l * 8 + 3] = dup(sig[l] / (lj2 * lj2));          //  F
            plD[l * 8 + 4] = dup(-Kcj);                          // -Kd
            plD[l * 8 + 5] = dup(1.0f / Mcj);                    //  Md
            plD[l * 8 + 6] = dup(lj2);                           //  lj2
            plD[l * 8 + 7] = dup(0.0f);
        }
        if (tid == 0) sig0d = dup(sig[0]);
    }

    // ---- stage x tiles ----
    const int n0 = blockIdx.y * TN, m0 = blockIdx.x * TM;
    if (tid < 128) {
        // nx2: k = tid>>4, p = tid&15
        int k = tid >> 4, p = tid & 15;
        int m = m0 + 2 * p;
        float a = (m     < M) ? x2[m * DD + k]       : 0.0f;
        float b = (m + 1 < M) ? x2[(m + 1) * DD + k] : 0.0f;
        nx2[k * 16 + p] = pack2(-a, -b);
    } else {
        int i = tid - 128;                // 0..127
        int r = i >> 3, k = i & 7;
        int n = n0 + r;
        x1d[r * DD + k] = dup((n < N) ? x1[n * DD + k] : 0.0f);
    }
    __syncthreads();

    const int n = n0 + ty;
    const int m = m0 + 2 * tx;
    if (n >= N || m >= M) return;

    const u64 negone = dup(-1.0f);

    // ---- d_k for the output pair ----
    u64 d[DD];
#pragma unroll
    for (int k = 0; k < DD; k++) {
        u64 diff;
        ADD2(diff, x1d[ty * DD + k], nx2[k * 16 + tx]);
        MUL2(d[k], diff, diff);
    }

    // ---- E_a = exp2( d . w_a ) ----
    u64 E[DD];
#pragma unroll
    for (int a = 0; a < DD; a++) {
        const ulonglong2* wr = reinterpret_cast<const ulonglong2*>(&wD[a * DD]);
        ulonglong2 p0 = wr[0], p1 = wr[1], p2 = wr[2], p3 = wr[3];
        u64 s;
        MUL2(s, d[0], p0.x);
        FMA2(s, d[1], p0.y, s);
        FMA2(s, d[2], p1.x, s);
        FMA2(s, d[3], p1.y, s);
        FMA2(s, d[4], p2.x, s);
        FMA2(s, d[5], p2.y, s);
        FMA2(s, d[6], p3.x, s);
        FMA2(s, d[7], p3.y, s);
        float slo, shi;
        unpack2(s, slo, shi);
        E[a] = pack2(ex2a(slo), ex2a(shi));
    }

    // ---- Q_c = d_c * E_c ----
    u64 Q[DD];
#pragma unroll
    for (int c = 0; c < DD; c++) MUL2(Q[c], d[c], E[c]);

    // ---- S = sum_j (KMm_col_j . E  -  Km_col_j . Q) * E_j * (lj2_j - d_j) ----
    u64 S2 = dup(0.0f);
#pragma unroll
    for (int j = 0; j < DD; j++) {
        const ulonglong2* kr = reinterpret_cast<const ulonglong2*>(&ksD[j * 16]);
        ulonglong2 a0 = kr[0], a1 = kr[1], a2 = kr[2], a3 = kr[3]; // KMm
        ulonglong2 b0 = kr[4], b1 = kr[5], b2 = kr[6], b3 = kr[7]; // -Km
        u64 acc;
        MUL2(acc, a0.x, E[0]);
        FMA2(acc, a0.y, E[1], acc);
        FMA2(acc, a1.x, E[2], acc);
        FMA2(acc, a1.y, E[3], acc);
        FMA2(acc, a2.x, E[4], acc);
        FMA2(acc, a2.y, E[5], acc);
        FMA2(acc, a3.x, E[6], acc);
        FMA2(acc, a3.y, E[7], acc);
        FMA2(acc, b0.x, Q[0], acc);
        FMA2(acc, b0.y, Q[1], acc);
        FMA2(acc, b1.x, Q[2], acc);
        FMA2(acc, b1.y, Q[3], acc);
        FMA2(acc, b2.x, Q[4], acc);
        FMA2(acc, b2.y, Q[5], acc);
        FMA2(acc, b3.x, Q[6], acc);
        FMA2(acc, b3.y, Q[7], acc);
        u64 t;
        FMA2(t, d[j], negone, plD[j * 8 + 6]);   // lj2_j - d_j
        u64 et;
        MUL2(et, E[j], t);
        FMA2(S2, acc, et, S2);
    }

    // ---- corr ----
    u64 corr2 = dup(0.0f);
#pragma unroll
    for (int l = 0; l < DD; l++) {
        const ulonglong2* pr = reinterpret_cast<const ulonglong2*>(&plD[l * 8]);
        ulonglong2 q0 = pr[0];   // (-c1, c2)
        ulonglong2 q1 = pr[1];   // (c3, F)
        ulonglong2 q2 = pr[2];   // (-Kd, Md)
        ulonglong2 q3 = pr[3];   // (lj2, 0)
        u64 E2;
        MUL2(E2, E[l], E[l]);
        u64 u;
        FMA2(u, d[l], q0.y, q0.x);               // c2*d - c1
        u64 poly;
        FMA2(poly, d[l], u, q1.x);               // d*(c2*d - c1) + c3
        u64 dd;
        MUL2(dd, poly, q1.y);                    // F * poly
        u64 t1, t2, t3;
        FMA2(t1, d[l], negone, q2.y);            // Md - d
        FMA2(t2, d[l], negone, q3.x);            // lj2 - d
        MUL2(t3, t1, t2);
        FMA2(dd, t3, q2.x, dd);                  // dd - Kd*t3
        FMA2(corr2, dd, E2, corr2);
    }

    // ---- out = sig0 * E0 * (S + corr) ----
    u64 sum;
    ADD2(sum, S2, corr2);
    u64 sE0;
    MUL2(sE0, E[0], sig0d);
    u64 res;
    MUL2(res, sum, sE0);

    long idx = (long)n * M + m;
    if (m + 1 < M) {
        *reinterpret_cast<u64*>(&out[idx]) = res;   // STG.64 (idx even -> 8B aligned)
    } else {
        float lo, hi;
        unpack2(res, lo, hi);
        out[idx] = lo;
    }
}

extern "C" void kernel_launch(void* const* d_in, const int* in_sizes, int n_in,
                              void* d_out, int out_size)
{
    const float* x1  = (const float*)d_in[0];
    const float* x2  = (const float*)d_in[1];
    const float* L   = (const float*)d_in[2];
    const float* sig = (const float*)d_in[3];
    float* out = (float*)d_out;

    int N = in_sizes[0] / DD;
    int M = in_sizes[1] / DD;

    dim3 block(TN, TN);                                   // 256 threads
    dim3 grid((M + TM - 1) / TM, (N + TN - 1) / TN);
    taylor_rbf_kernel<<<grid, block>>>(x1, x2, L, sig, out, N, M);
}